// round 9
// baseline (speedup 1.0000x reference)
#include <cuda_runtime.h>
#include <cstdint>
#include <math.h>

#define Bb 128
#define Tt 25
#define Ee 512
#define Hh 1024
#define Vv 10000
#define Ff 2048

// ---------------- device scratch ----------------
__device__ float g_wbuf[36331520];     // tf32-rounded weights + embedding
__device__ float g_featin[Bb*Ff];
__device__ float g_feat[Bb*Hh];
__device__ float g_prefeat[Bb*4096];   // feat @ W0i[512:1536] + bias0i
__device__ float g_pre0[Tt*Bb*4096];   // full input-part of layer0 gates
__device__ float g_c0[Bb*Hh];
__device__ float g_c1[Bb*Hh];
__device__ float g_comb1[Bb*2048];     // [h0 | h1]
__device__ float g_hs[Tt*Bb*Hh];
__device__ float g_part[32*16384];     // G1 k-split partials (32 x [128x128])
__device__ float g_bias0i[4096];
__device__ float g_bias1i[4096];
__device__ unsigned g_bgrp[8*64];      // barrier group counters, 256B stride
__device__ unsigned g_barc;            // barrier root
__device__ unsigned g_hbar;            // head kernel barrier

// wbuf offsets (floats)
#define OF_WP   0
#define OF_W0I  2097152      /* 2560x4096 interleaved */
#define OF_W1I  12582912     /* 2048x4096 interleaved */
#define OF_WOUT 20971520     /* 1024x10000 -> ends at 31211520 */
#define OF_EMB  31211520     /* 10000x512 rounded embedding */

__device__ __forceinline__ uint32_t f2tf(float x){
    uint32_t u; asm("cvt.rna.tf32.f32 %0, %1;" : "=r"(u) : "f"(x)); return u;
}
__device__ __forceinline__ float roundtf(float x){ return __uint_as_float(f2tf(x)); }
__device__ __forceinline__ float sigf(float x){ return 1.0f/(1.0f + expf(-x)); }

__device__ __forceinline__ void cp16(float* sdst, const float* gsrc){
    uint32_t s = (uint32_t)__cvta_generic_to_shared(sdst);
    asm volatile("cp.async.cg.shared.global [%0], [%1], 16;\n" :: "r"(s), "l"(gsrc));
}
__device__ __forceinline__ void cp16p(float* sdst, const float* gsrc, bool pred){
    uint32_t s = (uint32_t)__cvta_generic_to_shared(sdst);
    int sz = pred ? 16 : 0;
    asm volatile("cp.async.cg.shared.global [%0], [%1], 16, %2;\n" :: "r"(s), "l"(gsrc), "r"(sz));
}
__device__ __forceinline__ void cp_commit(){ asm volatile("cp.async.commit_group;\n"); }
__device__ __forceinline__ void cp_wait2(){ asm volatile("cp.async.wait_group 2;\n"); }
__device__ __forceinline__ void cp_wait0(){ asm volatile("cp.async.wait_group 0;\n"); }

// ---------------- one-shot convert / pack / zero kernel ----------------
#define S_FEAT 65536
#define S_WP   524288
#define S_WOUT 2560000
#define S_EMB  1280000
#define S_W0I  2621440
#define S_W1I  2097152
#define S_B    1024
#define S_Z    (32768+32768+65536+3+512)
#define CVT_TOTAL (S_FEAT+S_WP+S_WOUT+S_EMB+S_W0I+S_W1I+2*S_B+S_Z)

__global__ void cvt_all(
    const float* __restrict__ features, const float* __restrict__ Wp,
    const float* __restrict__ Wout, const float* __restrict__ emb,
    const float* __restrict__ Wf0, const float* __restrict__ Wi0,
    const float* __restrict__ Wo0, const float* __restrict__ Wg0,
    const float* __restrict__ Wf1, const float* __restrict__ Wi1,
    const float* __restrict__ Wo1, const float* __restrict__ Wg1,
    const float* __restrict__ bf0, const float* __restrict__ bi0,
    const float* __restrict__ bo0, const float* __restrict__ bg0,
    const float* __restrict__ bf1, const float* __restrict__ bi1,
    const float* __restrict__ bo1, const float* __restrict__ bg1)
{
    int i = blockIdx.x*blockDim.x + threadIdx.x;
    if (i >= CVT_TOTAL) return;
    if (i < S_FEAT){
        float4 v = reinterpret_cast<const float4*>(features)[i];
        v.x=roundtf(v.x); v.y=roundtf(v.y); v.z=roundtf(v.z); v.w=roundtf(v.w);
        reinterpret_cast<float4*>(g_featin)[i] = v; return;
    }
    i -= S_FEAT;
    if (i < S_WP){
        float4 v = reinterpret_cast<const float4*>(Wp)[i];
        v.x=roundtf(v.x); v.y=roundtf(v.y); v.z=roundtf(v.z); v.w=roundtf(v.w);
        reinterpret_cast<float4*>(g_wbuf + OF_WP)[i] = v; return;
    }
    i -= S_WP;
    if (i < S_WOUT){
        float4 v = reinterpret_cast<const float4*>(Wout)[i];
        v.x=roundtf(v.x); v.y=roundtf(v.y); v.z=roundtf(v.z); v.w=roundtf(v.w);
        reinterpret_cast<float4*>(g_wbuf + OF_WOUT)[i] = v; return;
    }
    i -= S_WOUT;
    if (i < S_EMB){
        float4 v = reinterpret_cast<const float4*>(emb)[i];
        v.x=roundtf(v.x); v.y=roundtf(v.y); v.z=roundtf(v.z); v.w=roundtf(v.w);
        reinterpret_cast<float4*>(g_wbuf + OF_EMB)[i] = v; return;
    }
    i -= S_EMB;
    if (i < S_W0I){
        int k = i >> 10, h = i & 1023;
        int s = k*1024 + h;
        float4 v;
        v.x = roundtf(Wf0[s]); v.y = roundtf(Wi0[s]);
        v.z = roundtf(Wo0[s]); v.w = roundtf(Wg0[s]);
        reinterpret_cast<float4*>(g_wbuf + OF_W0I)[(size_t)k*1024 + h] = v; return;
    }
    i -= S_W0I;
    if (i < S_W1I){
        int k = i >> 10, h = i & 1023;
        int s = k*1024 + h;
        float4 v;
        v.x = roundtf(Wf1[s]); v.y = roundtf(Wi1[s]);
        v.z = roundtf(Wo1[s]); v.w = roundtf(Wg1[s]);
        reinterpret_cast<float4*>(g_wbuf + OF_W1I)[(size_t)k*1024 + h] = v; return;
    }
    i -= S_W1I;
    if (i < S_B){
        float4 v; v.x=bf0[i]; v.y=bi0[i]; v.z=bo0[i]; v.w=bg0[i];
        reinterpret_cast<float4*>(g_bias0i)[i] = v; return;
    }
    i -= S_B;
    if (i < S_B){
        float4 v; v.x=bf1[i]; v.y=bi1[i]; v.z=bo1[i]; v.w=bg1[i];
        reinterpret_cast<float4*>(g_bias1i)[i] = v; return;
    }
    i -= S_B;
    {
        float4 z = make_float4(0.f,0.f,0.f,0.f);
        if (i < 32768){ reinterpret_cast<float4*>(g_c0)[i] = z; return; }
        i -= 32768;
        if (i < 32768){ reinterpret_cast<float4*>(g_c1)[i] = z; return; }
        i -= 32768;
        if (i < 65536){ reinterpret_cast<float4*>(g_comb1)[i] = z; return; }
        i -= 65536;
        if (i == 0){ g_barc = 0u; return; }
        if (i == 1){ g_hbar = 0u; return; }
        if (i == 2) return;
        g_bgrp[i-3] = 0u;
    }
}

// ---------------- shared GEMM smem + 128x128x16 bodies ----------------
#define MODE_LEAKY 1
#define MODE_REMAP 4

struct SmemGemm {
    float As[4][128][20];
    float Ws[4][16][136];
};

// Full body with epilogue-store (used by head/pre0 standalone kernels)
__device__ __forceinline__ void gemm128_body(
    const float* __restrict__ A, int lda, int K,
    const float* __restrict__ W, int ldw,
    const float* __restrict__ bias, const float* __restrict__ rowext,
    float* __restrict__ C, int ldc, int N, int mode,
    int n0, int m0,
    const int* __restrict__ gtok, const float* __restrict__ embW,
    SmemGemm& s)
{
    const int tid  = threadIdx.x;
    const int lane = tid & 31, warp = tid >> 5;
    const int wm = warp & 3, wn = warp >> 2;
    const int g  = lane >> 2, tg = lane & 3;

    const int ar = tid >> 1,  ac = (tid & 1) * 8;
    const int wr = tid >> 4,  wc = (tid & 15) * 8;
    const bool wp0 = (n0 + wc)     < N;
    const bool wp1 = (n0 + wc + 4) < N;
    const float* asrc;
    if (gtok){
        int t = m0 >> 7;
        int tok = gtok[ar*Tt + t];
        asrc = embW + (size_t)tok*Ee + ac;
    } else {
        asrc = A + (size_t)(m0+ar)*lda + ac;
    }
    const float* wsrc = W + (size_t)wr*ldw + n0 + wc;

    float acc[2][8][4];
    #pragma unroll
    for (int mi=0;mi<2;mi++)
        #pragma unroll
        for (int ni=0;ni<8;ni++)
            #pragma unroll
            for (int j=0;j<4;j++) acc[mi][ni][j]=0.f;

    const int nk = K >> 4;
    #pragma unroll
    for (int st2=0; st2<3; ++st2){
        cp16 (&s.As[st2][ar][ac],   asrc + st2*16);
        cp16 (&s.As[st2][ar][ac+4], asrc + st2*16 + 4);
        cp16p(&s.Ws[st2][wr][wc],   wp0 ? (wsrc + (size_t)(st2*16)*ldw)     : W, wp0);
        cp16p(&s.Ws[st2][wr][wc+4], wp1 ? (wsrc + (size_t)(st2*16)*ldw + 4) : W, wp1);
        cp_commit();
    }

    for (int kt=0; kt<nk; ++kt){
        cp_wait2();
        __syncthreads();
        int kn = kt + 3;
        if (kn < nk){
            int sn = kn & 3;
            cp16 (&s.As[sn][ar][ac],   asrc + kn*16);
            cp16 (&s.As[sn][ar][ac+4], asrc + kn*16 + 4);
            cp16p(&s.Ws[sn][wr][wc],   wp0 ? (wsrc + (size_t)(kn*16)*ldw)     : W, wp0);
            cp16p(&s.Ws[sn][wr][wc+4], wp1 ? (wsrc + (size_t)(kn*16)*ldw + 4) : W, wp1);
        }
        cp_commit();
        const int st = kt & 3;
        #pragma unroll
        for (int kk=0; kk<2; ++kk){
            const int kc = kk*8 + tg;
            uint32_t afr[2][4];
            #pragma unroll
            for (int mi=0; mi<2; ++mi){
                const int rr = wm*32 + mi*16 + g;
                afr[mi][0] = __float_as_uint(s.As[st][rr  ][kc  ]);
                afr[mi][1] = __float_as_uint(s.As[st][rr+8][kc  ]);
                afr[mi][2] = __float_as_uint(s.As[st][rr  ][kc+4]);
                afr[mi][3] = __float_as_uint(s.As[st][rr+8][kc+4]);
            }
            #pragma unroll
            for (int ni=0; ni<8; ++ni){
                const int nc = wn*64 + ni*8 + g;
                uint32_t b0 = __float_as_uint(s.Ws[st][kc  ][nc]);
                uint32_t b1 = __float_as_uint(s.Ws[st][kc+4][nc]);
                #pragma unroll
                for (int mi=0; mi<2; ++mi){
                    asm volatile(
                        "mma.sync.aligned.m16n8k8.row.col.f32.tf32.tf32.f32 "
                        "{%0,%1,%2,%3}, {%4,%5,%6,%7}, {%8,%9}, {%0,%1,%2,%3};\n"
                        : "+f"(acc[mi][ni][0]), "+f"(acc[mi][ni][1]),
                          "+f"(acc[mi][ni][2]), "+f"(acc[mi][ni][3])
                        : "r"(afr[mi][0]), "r"(afr[mi][1]),
                          "r"(afr[mi][2]), "r"(afr[mi][3]), "r"(b0), "r"(b1));
                }
            }
        }
    }
    cp_wait0();
    __syncthreads();

    #pragma unroll
    for (int mi=0; mi<2; ++mi){
        const int grow0 = m0 + wm*32 + mi*16 + g;
        const int grow1 = grow0 + 8;
        size_t drow0, drow1;
        if (mode & MODE_REMAP){
            drow0 = (size_t)((grow0 & 127)*Tt + (grow0 >> 7));
            drow1 = (size_t)((grow1 & 127)*Tt + (grow1 >> 7));
        } else { drow0 = (size_t)grow0; drow1 = (size_t)grow1; }
        float* C0 = C + drow0*ldc;
        float* C1 = C + drow1*ldc;
        #pragma unroll
        for (int ni=0; ni<8; ++ni){
            const int gcol = n0 + wn*64 + ni*8 + 2*tg;
            if (gcol >= N) continue;
            float v00=acc[mi][ni][0], v01=acc[mi][ni][1];
            float v10=acc[mi][ni][2], v11=acc[mi][ni][3];
            if (bias){
                float b0v = bias[gcol], b1v = bias[gcol+1];
                v00+=b0v; v01+=b1v; v10+=b0v; v11+=b1v;
            }
            if (rowext){
                const float* r0 = rowext + (size_t)(grow0 & 127)*4096;
                const float* r1 = rowext + (size_t)(grow1 & 127)*4096;
                v00 += r0[gcol]; v01 += r0[gcol+1];
                v10 += r1[gcol]; v11 += r1[gcol+1];
            }
            if (mode & MODE_LEAKY){
                v00 = roundtf(v00 > 0.f ? v00 : 0.01f*v00);
                v01 = roundtf(v01 > 0.f ? v01 : 0.01f*v01);
                v10 = roundtf(v10 > 0.f ? v10 : 0.01f*v10);
                v11 = roundtf(v11 > 0.f ? v11 : 0.01f*v11);
            }
            C0[gcol] = v00; C0[gcol+1] = v01;
            C1[gcol] = v10; C1[gcol+1] = v11;
        }
    }
}

__global__ __launch_bounds__(256) void gemm128k(
    const float* __restrict__ A, int lda, int K,
    const float* __restrict__ W, int ldw,
    const float* __restrict__ bias, const float* __restrict__ rowext,
    float* __restrict__ C, int ldc, int N, int mode,
    const int* __restrict__ gtok, const float* __restrict__ embW)
{
    __shared__ SmemGemm s;
    gemm128_body(A, lda, K, W, ldw, bias, rowext, C, ldc, N, mode,
                 blockIdx.x*128, blockIdx.y*128, gtok, embW, s);
}

__global__ __launch_bounds__(256) void head_kernel(const float* __restrict__ bp)
{
    __shared__ SmemGemm s;
    const int cta = blockIdx.x;
    if (cta < 8){
        gemm128_body(g_featin, Ff, Ff, g_wbuf + OF_WP, Hh, bp, nullptr,
                     g_feat, Hh, Hh, MODE_LEAKY, cta*128, 0, nullptr, nullptr, s);
    }
    __syncthreads();
    if (threadIdx.x == 0){
        __threadfence();
        atomicAdd(&g_hbar, 1u);
        unsigned v;
        do {
            asm volatile("ld.acquire.gpu.u32 %0, [%1];" : "=r"(v) : "l"(&g_hbar) : "memory");
        } while (v < 40u);
    }
    __syncthreads();
    if (cta >= 8){
        gemm128_body(g_feat, Hh, Hh, g_wbuf + OF_W0I + (size_t)512*4096, 4096,
                     g_bias0i, nullptr, g_prefeat, 4096, 4096, 0,
                     (cta-8)*128, 0, nullptr, nullptr, s);
    }
}

// ---------------- persistent: recurrence + streamed out-GEMM ----------------
#define RNCTA 175
#define NGRP  7

__device__ __forceinline__ void gridbar(unsigned &ep, int cta){
    __syncthreads();
    ep += 1;
    if (threadIdx.x == 0){
        __threadfence();
        const int grp = cta / 25;
        unsigned* gc = &g_bgrp[grp*64];
        atomicAdd(gc, 1u);
        unsigned v;
        if (cta == grp*25){
            do {
                asm volatile("ld.acquire.gpu.u32 %0, [%1];" : "=r"(v) : "l"(gc) : "memory");
            } while (v < ep*25u);
            __threadfence();
            atomicAdd(&g_barc, 1u);
        }
        do {
            asm volatile("ld.acquire.gpu.u32 %0, [%1];" : "=r"(v) : "l"(&g_barc) : "memory");
        } while (v < ep*(unsigned)NGRP);
    }
    __syncthreads();
}

// Mainloop-only 128x128, K=1024 (64 iters). acc returned to caller.
__device__ __forceinline__ void g128_main(
    const float* __restrict__ A, int lda,
    const float* __restrict__ W, int ldw, int Nw,
    int n0, int m0, SmemGemm& s, float acc[2][8][4])
{
    const int tid  = threadIdx.x;
    const int lane = tid & 31, warp = tid >> 5;
    const int wm = warp & 3, wn = warp >> 2;
    const int g  = lane >> 2, tg = lane & 3;
    const int ar = tid >> 1,  ac = (tid & 1) * 8;
    const int wr = tid >> 4,  wc = (tid & 15) * 8;
    const bool wp0 = (n0 + wc)     < Nw;
    const bool wp1 = (n0 + wc + 4) < Nw;
    const float* asrc = A + (size_t)(m0+ar)*lda + ac;
    const float* wsrc = W + (size_t)wr*ldw + n0 + wc;

    #pragma unroll
    for (int mi=0;mi<2;mi++)
        #pragma unroll
        for (int ni=0;ni<8;ni++)
            #pragma unroll
            for (int j=0;j<4;j++) acc[mi][ni][j]=0.f;

    #pragma unroll
    for (int st2=0; st2<3; ++st2){
        cp16 (&s.As[st2][ar][ac],   asrc + st2*16);
        cp16 (&s.As[st2][ar][ac+4], asrc + st2*16 + 4);
        cp16p(&s.Ws[st2][wr][wc],   wp0 ? (wsrc + (size_t)(st2*16)*ldw)     : W, wp0);
        cp16p(&s.Ws[st2][wr][wc+4], wp1 ? (wsrc + (size_t)(st2*16)*ldw + 4) : W, wp1);
        cp_commit();
    }
    for (int kt=0; kt<64; ++kt){
        cp_wait2();
        __syncthreads();
        int kn = kt + 3;
        if (kn < 64){
            int sn = kn & 3;
            cp16 (&s.As[sn][ar][ac],   asrc + kn*16);
            cp16 (&s.As[sn][ar][ac+4], asrc + kn*16 + 4);
            cp16p(&s.Ws[sn][wr][wc],   wp0 ? (wsrc + (size_t)(kn*16)*ldw)     : W, wp0);
            cp16p(&s.Ws[sn][wr][wc+4], wp1 ? (wsrc + (size_t)(kn*16)*ldw + 4) : W, wp1);
        }
        cp_commit();
        const int st = kt & 3;
        #pragma unroll
        for (int kk=0; kk<2; ++kk){
            const int kc = kk*8 + tg;
            uint32_t afr[2][4];
            #pragma unroll
            for (int mi=0; mi<2; ++mi){
                const int rr = wm*32 + mi*16 + g;
                afr[mi][0] = __float_as_uint(s.As[st][rr  ][kc  ]);
                afr[mi][1] = __float_as_uint(s.As[st][rr+8][kc  ]);
                afr[mi][2] = __float_as_uint(s.As[st][rr  ][kc+4]);
                afr[mi][3] = __float_as_uint(s.As[st][rr+8][kc+4]);
            }
            #pragma unroll
            for (int ni=0; ni<8; ++ni){
                const int nc = wn*64 + ni*8 + g;
                uint32_t b0 = __float_as_uint(s.Ws[st][kc  ][nc]);
                uint32_t b1 = __float_as_uint(s.Ws[st][kc+4][nc]);
                #pragma unroll
                for (int mi=0; mi<2; ++mi){
                    asm volatile(
                        "mma.sync.aligned.m16n8k8.row.col.f32.tf32.tf32.f32 "
                        "{%0,%1,%2,%3}, {%4,%5,%6,%7}, {%8,%9}, {%0,%1,%2,%3};\n"
                        : "+f"(acc[mi][ni][0]), "+f"(acc[mi][ni][1]),
                          "+f"(acc[mi][ni][2]), "+f"(acc[mi][ni][3])
                        : "r"(afr[mi][0]), "r"(afr[mi][1]),
                          "r"(afr[mi][2]), "r"(afr[mi][3]), "r"(b0), "r"(b1));
                }
            }
        }
    }
    cp_wait0();
    __syncthreads();
}

__device__ __forceinline__ void store_part128(float acc[2][8][4], int tile)
{
    const int lane = threadIdx.x & 31, warp = threadIdx.x >> 5;
    const int wm = warp & 3, wn = warp >> 2;
    const int g  = lane >> 2, tg = lane & 3;
    float* gp = g_part + (size_t)tile*16384;
    #pragma unroll
    for (int mi=0; mi<2; ++mi){
        const int lr0 = wm*32 + mi*16 + g, lr1 = lr0 + 8;
        #pragma unroll
        for (int ni=0; ni<8; ++ni){
            const int lc = wn*64 + ni*8 + 2*tg;
            gp[lr0*128 + lc]   = acc[mi][ni][0];
            gp[lr0*128 + lc+1] = acc[mi][ni][1];
            gp[lr1*128 + lc]   = acc[mi][ni][2];
            gp[lr1*128 + lc+1] = acc[mi][ni][3];
        }
    }
}

// LSTM epilogue for a 128(M=B) x 128(N) gate tile. isG0: +pre0[i]; else +partial+bias1.
__device__ __forceinline__ void epi128(float acc[2][8][4], bool isG0, int tile,
                                       int i, int n0)
{
    const int lane = threadIdx.x & 31, warp = threadIdx.x >> 5;
    const int wm = warp & 3, wn = warp >> 2;
    const int g  = lane >> 2, tg = lane & 3;
    const float* gp  = g_part + (size_t)tile*16384;
    const float* pre = g_pre0 + (size_t)i*(Bb*4096);
    float* cbuf = isG0 ? g_c0 : g_c1;
    const int hoff = isG0 ? 0 : 1024;
    #pragma unroll
    for (int mi=0; mi<2; ++mi){
        const int b0r = wm*32 + mi*16 + g, b1r = b0r + 8;   // batch rows
        #pragma unroll
        for (int ni=0; ni<8; ++ni){
            const int lc = wn*64 + ni*8 + 2*tg;
            const int gcol = n0 + lc;
            float v00 = acc[mi][ni][0], v01 = acc[mi][ni][1];
            float v10 = acc[mi][ni][2], v11 = acc[mi][ni][3];
            if (isG0){
                v00 += pre[(size_t)b0r*4096 + gcol];
                v01 += pre[(size_t)b0r*4096 + gcol+1];
                v10 += pre[(size_t)b1r*4096 + gcol];
                v11 += pre[(size_t)b1r*4096 + gcol+1];
            } else {
                float bb0 = g_bias1i[gcol], bb1 = g_bias1i[gcol+1];
                v00 += gp[b0r*128 + lc]   + bb0;
                v01 += gp[b0r*128 + lc+1] + bb1;
                v10 += gp[b1r*128 + lc]   + bb0;
                v11 += gp[b1r*128 + lc+1] + bb1;
            }
            float p00 = __shfl_xor_sync(0xffffffffu, v00, 1);
            float p01 = __shfl_xor_sync(0xffffffffu, v01, 1);
            float p10 = __shfl_xor_sync(0xffffffffu, v10, 1);
            float p11 = __shfl_xor_sync(0xffffffffu, v11, 1);
            if ((tg & 1) == 0){
                const int h = (n0 >> 2) + wn*16 + ni*2 + (tg >> 1);
                {
                    float f = sigf(v00), ii = sigf(v01);
                    float o = sigf(p00), gg = tanhf(p01);
                    float c = f*cbuf[b0r*1024 + h] + ii*gg;
                    cbuf[b0r*1024 + h] = c;
                    float hn = roundtf(o * tanhf(c));
                    g_comb1[b0r*2048 + hoff + h] = hn;
                    if (!isG0) g_hs[(size_t)(i-1)*(Bb*Hh) + b0r*1024 + h] = hn;
                }
                {
                    float f = sigf(v10), ii = sigf(v11);
                    float o = sigf(p10), gg = tanhf(p11);
                    float c = f*cbuf[b1r*1024 + h] + ii*gg;
                    cbuf[b1r*1024 + h] = c;
                    float hn = roundtf(o * tanhf(c));
                    g_comb1[b1r*2048 + hoff + h] = hn;
                    if (!isG0) g_hs[(size_t)(i-1)*(Bb*Hh) + b1r*1024 + h] = hn;
                }
            }
        }
    }
}

// logits store: bias + (t*128+b)->(b*25+t) remap
__device__ __forceinline__ void out_store128(float acc[2][8][4],
    const float* __restrict__ bias, float* __restrict__ C, int n0, int m0)
{
    const int lane = threadIdx.x & 31, warp = threadIdx.x >> 5;
    const int wm = warp & 3, wn = warp >> 2;
    const int g  = lane >> 2, tg = lane & 3;
    #pragma unroll
    for (int mi=0; mi<2; ++mi){
        const int grow0 = m0 + wm*32 + mi*16 + g;
        const int grow1 = grow0 + 8;
        float* C0 = C + (size_t)((grow0 & 127)*Tt + (grow0 >> 7))*Vv;
        float* C1 = C + (size_t)((grow1 & 127)*Tt + (grow1 >> 7))*Vv;
        #pragma unroll
        for (int ni=0; ni<8; ++ni){
            const int gcol = n0 + wn*64 + ni*8 + 2*tg;
            if (gcol >= Vv) continue;
            float b0v = bias[gcol], b1v = bias[gcol+1];
            C0[gcol]   = acc[mi][ni][0] + b0v;
            C0[gcol+1] = acc[mi][ni][1] + b1v;
            C1[gcol]   = acc[mi][ni][2] + b0v;
            C1[gcol+1] = acc[mi][ni][3] + b1v;
        }
    }
}

__global__ __launch_bounds__(256, 2) void lstm_persistent(
    float* __restrict__ out, const float* __restrict__ bout)
{
    __shared__ SmemGemm s;
    const int cta = blockIdx.x;
    unsigned ep = 0;
    float acc[2][8][4];

    if (cta < 32){
        // G0: layer-0 recurrent gates for step i  (phases 0..24)
        const int n0 = cta*128;
        const float* Wb = g_wbuf + OF_W0I + (size_t)1536*4096;
        for (int i = 0; i <= 26; ++i){
            const bool work = (i <= 24);
            if (work) g128_main(g_comb1, 2048, Wb, 4096, 1<<30, n0, 0, s, acc);
            gridbar(ep, cta);
            if (work) epi128(acc, true, 0, i, n0);
            gridbar(ep, cta);
        }
    } else if (cta < 96){
        // G1: layer-1 gates for step i-1  (phases 1..25), ksplit 2
        const int u = cta - 32, ks = u & 1, tile = u >> 1;
        const int n0 = tile*128;
        const float* Wb = g_wbuf + OF_W1I + (size_t)ks*1024*4096;
        const float* Ab = g_comb1 + ks*1024;
        for (int i = 0; i <= 26; ++i){
            const bool work = (i >= 1 && i <= 25);
            if (work){
                g128_main(Ab, 2048, Wb, 4096, 1<<30, n0, 0, s, acc);
                if (ks == 1) store_part128(acc, tile);
            }
            gridbar(ep, cta);
            if (work && ks == 0) epi128(acc, false, tile, i, n0);
            gridbar(ep, cta);
        }
    } else {
        // OUT: logits tile (t = i-2, n-block j)  (phases 2..26)
        const int j = cta - 96;
        const int n0 = j*128;
        const float* Wb = g_wbuf + OF_WOUT;
        for (int i = 0; i <= 26; ++i){
            const bool work = (i >= 2);
            if (work){
                const int m0 = (i-2)*128;
                g128_main(g_hs, 1024, Wb, Vv, Vv, n0, m0, s, acc);
                out_store128(acc, bout, out, n0, m0);
            }
            gridbar(ep, cta);
            gridbar(ep, cta);
        }
    }
}

// ---------------- host orchestration ----------------
extern "C" void kernel_launch(void* const* d_in, const int* in_sizes, int n_in,
                              void* d_out, int out_size)
{
    const int*   tokens    = (const int*)  d_in[0];
    const float* features  = (const float*)d_in[1];
    const float* embedding = (const float*)d_in[2];
    const float* Wp  = (const float*)d_in[3];
    const float* bp  = (const float*)d_in[4];
    const float* Wf0 = (const float*)d_in[5];  const float* bf0 = (const float*)d_in[6];
    const float* Wi0 = (const float*)d_in[7];  const float* bi0 = (const float*)d_in[8];
    const float* Wo0 = (const float*)d_in[9];  const float* bo0 = (const float*)d_in[10];
    const float* Wg0 = (const float*)d_in[11]; const float* bg0 = (const float*)d_in[12];
    const float* Wf1 = (const float*)d_in[13]; const float* bf1 = (const float*)d_in[14];
    const float* Wi1 = (const float*)d_in[15]; const float* bi1 = (const float*)d_in[16];
    const float* Wo1 = (const float*)d_in[17]; const float* bo1 = (const float*)d_in[18];
    const float* Wg1 = (const float*)d_in[19]; const float* bg1 = (const float*)d_in[20];
    const float* Wout = (const float*)d_in[21];
    const float* bout = (const float*)d_in[22];
    float* out = (float*)d_out;

    float *wb, *pre0, *prefeat;
    cudaGetSymbolAddress((void**)&wb,      g_wbuf);
    cudaGetSymbolAddress((void**)&pre0,    g_pre0);
    cudaGetSymbolAddress((void**)&prefeat, g_prefeat);

    // 1) convert + pack + zero
    cvt_all<<<(CVT_TOTAL + 255)/256, 256>>>(features, Wp, Wout, embedding,
        Wf0, Wi0, Wo0, Wg0, Wf1, Wi1, Wo1, Wg1,
        bf0, bi0, bo0, bg0, bf1, bi1, bo1, bg1);

    // 2) head: feat projection + prefeat
    head_kernel<<<40, 256>>>(bp);

    // 3) pre0 = gather(emb) @ W0i[0:512,:] + prefeat[b]
    gemm128k<<<dim3(32,25), 256>>>(nullptr, 0, 512,
        wb + OF_W0I, 4096, nullptr, prefeat,
        pre0, 4096, 4096, 0, tokens, wb + OF_EMB);

    // 4) persistent: recurrence + streamed logits   <-- profiled slot
    lstm_persistent<<<RNCTA, 256>>>(out, bout);
}

// round 11
// speedup vs baseline: 1.4520x; 1.4520x over previous
#include <cuda_runtime.h>
#include <cstdint>
#include <math.h>

#define Bb 128
#define Tt 25
#define Ee 512
#define Hh 1024
#define Vv 10000
#define Ff 2048

// ---------------- device scratch ----------------
__device__ float g_wbuf[36331520];     // tf32-rounded weights + embedding
__device__ float g_featin[Bb*Ff];
__device__ float g_feat[Bb*Hh];
__device__ float g_prefeat[Bb*4096];   // feat @ W0i[512:1536] + bias0i
__device__ float g_pre0[Tt*Bb*4096];   // full input-part of layer0 gates
__device__ float g_c0[Bb*Hh];
__device__ float g_c1[Bb*Hh];
__device__ float g_comb1[Bb*2048];     // [h0 | h1]
__device__ float g_hs[Tt*Bb*Hh];
__device__ float g_part[128*4096];     // k-split partial tiles
__device__ float g_bias0i[4096];
__device__ float g_bias1i[4096];
__device__ unsigned g_bgrp[8*64];      // barrier group counters, 256B stride
__device__ unsigned g_barc;            // barrier root
__device__ unsigned g_hbar;            // head kernel barrier

// wbuf offsets (floats)
#define OF_WP   0
#define OF_W0I  2097152      /* 2560x4096 interleaved */
#define OF_W1I  12582912     /* 2048x4096 interleaved */
#define OF_WOUT 20971520     /* 1024x10000 -> ends at 31211520 */
#define OF_EMB  31211520     /* 10000x512 rounded embedding */

__device__ __forceinline__ uint32_t f2tf(float x){
    uint32_t u; asm("cvt.rna.tf32.f32 %0, %1;" : "=r"(u) : "f"(x)); return u;
}
__device__ __forceinline__ float roundtf(float x){ return __uint_as_float(f2tf(x)); }
__device__ __forceinline__ float sigf(float x){ return 1.0f/(1.0f + expf(-x)); }

__device__ __forceinline__ void cp16(float* sdst, const float* gsrc){
    uint32_t s = (uint32_t)__cvta_generic_to_shared(sdst);
    asm volatile("cp.async.cg.shared.global [%0], [%1], 16;\n" :: "r"(s), "l"(gsrc));
}
__device__ __forceinline__ void cp16p(float* sdst, const float* gsrc, bool pred){
    uint32_t s = (uint32_t)__cvta_generic_to_shared(sdst);
    int sz = pred ? 16 : 0;
    asm volatile("cp.async.cg.shared.global [%0], [%1], 16, %2;\n" :: "r"(s), "l"(gsrc), "r"(sz));
}
__device__ __forceinline__ void cp_commit(){ asm volatile("cp.async.commit_group;\n"); }
__device__ __forceinline__ void cp_wait2(){ asm volatile("cp.async.wait_group 2;\n"); }
__device__ __forceinline__ void cp_wait0(){ asm volatile("cp.async.wait_group 0;\n"); }

// ---------------- one-shot convert / pack / zero kernel ----------------
#define S_FEAT 65536
#define S_WP   524288
#define S_WOUT 2560000
#define S_EMB  1280000
#define S_W0I  2621440
#define S_W1I  2097152
#define S_B    1024
#define S_Z    (32768+32768+65536+3+512)
#define CVT_TOTAL (S_FEAT+S_WP+S_WOUT+S_EMB+S_W0I+S_W1I+2*S_B+S_Z)

__global__ void cvt_all(
    const float* __restrict__ features, const float* __restrict__ Wp,
    const float* __restrict__ Wout, const float* __restrict__ emb,
    const float* __restrict__ Wf0, const float* __restrict__ Wi0,
    const float* __restrict__ Wo0, const float* __restrict__ Wg0,
    const float* __restrict__ Wf1, const float* __restrict__ Wi1,
    const float* __restrict__ Wo1, const float* __restrict__ Wg1,
    const float* __restrict__ bf0, const float* __restrict__ bi0,
    const float* __restrict__ bo0, const float* __restrict__ bg0,
    const float* __restrict__ bf1, const float* __restrict__ bi1,
    const float* __restrict__ bo1, const float* __restrict__ bg1)
{
    int i = blockIdx.x*blockDim.x + threadIdx.x;
    if (i >= CVT_TOTAL) return;
    if (i < S_FEAT){
        float4 v = reinterpret_cast<const float4*>(features)[i];
        v.x=roundtf(v.x); v.y=roundtf(v.y); v.z=roundtf(v.z); v.w=roundtf(v.w);
        reinterpret_cast<float4*>(g_featin)[i] = v; return;
    }
    i -= S_FEAT;
    if (i < S_WP){
        float4 v = reinterpret_cast<const float4*>(Wp)[i];
        v.x=roundtf(v.x); v.y=roundtf(v.y); v.z=roundtf(v.z); v.w=roundtf(v.w);
        reinterpret_cast<float4*>(g_wbuf + OF_WP)[i] = v; return;
    }
    i -= S_WP;
    if (i < S_WOUT){
        float4 v = reinterpret_cast<const float4*>(Wout)[i];
        v.x=roundtf(v.x); v.y=roundtf(v.y); v.z=roundtf(v.z); v.w=roundtf(v.w);
        reinterpret_cast<float4*>(g_wbuf + OF_WOUT)[i] = v; return;
    }
    i -= S_WOUT;
    if (i < S_EMB){
        float4 v = reinterpret_cast<const float4*>(emb)[i];
        v.x=roundtf(v.x); v.y=roundtf(v.y); v.z=roundtf(v.z); v.w=roundtf(v.w);
        reinterpret_cast<float4*>(g_wbuf + OF_EMB)[i] = v; return;
    }
    i -= S_EMB;
    if (i < S_W0I){
        int k = i >> 10, h = i & 1023;
        int s = k*1024 + h;
        float4 v;
        v.x = roundtf(Wf0[s]); v.y = roundtf(Wi0[s]);
        v.z = roundtf(Wo0[s]); v.w = roundtf(Wg0[s]);
        reinterpret_cast<float4*>(g_wbuf + OF_W0I)[(size_t)k*1024 + h] = v; return;
    }
    i -= S_W0I;
    if (i < S_W1I){
        int k = i >> 10, h = i & 1023;
        int s = k*1024 + h;
        float4 v;
        v.x = roundtf(Wf1[s]); v.y = roundtf(Wi1[s]);
        v.z = roundtf(Wo1[s]); v.w = roundtf(Wg1[s]);
        reinterpret_cast<float4*>(g_wbuf + OF_W1I)[(size_t)k*1024 + h] = v; return;
    }
    i -= S_W1I;
    if (i < S_B){
        float4 v; v.x=bf0[i]; v.y=bi0[i]; v.z=bo0[i]; v.w=bg0[i];
        reinterpret_cast<float4*>(g_bias0i)[i] = v; return;
    }
    i -= S_B;
    if (i < S_B){
        float4 v; v.x=bf1[i]; v.y=bi1[i]; v.z=bo1[i]; v.w=bg1[i];
        reinterpret_cast<float4*>(g_bias1i)[i] = v; return;
    }
    i -= S_B;
    {
        float4 z = make_float4(0.f,0.f,0.f,0.f);
        if (i < 32768){ reinterpret_cast<float4*>(g_c0)[i] = z; return; }
        i -= 32768;
        if (i < 32768){ reinterpret_cast<float4*>(g_c1)[i] = z; return; }
        i -= 32768;
        if (i < 65536){ reinterpret_cast<float4*>(g_comb1)[i] = z; return; }
        i -= 65536;
        if (i == 0){ g_barc = 0u; return; }
        if (i == 1){ g_hbar = 0u; return; }
        if (i == 2) return;
        g_bgrp[i-3] = 0u;
    }
}

// ---------------- 128x128x16 TF32 GEMM body ----------------
#define MODE_LEAKY 1
#define MODE_REMAP 4

struct SmemGemm {
    float As[4][128][20];
    float Ws[4][16][136];
};

__device__ __forceinline__ void gemm128_body(
    const float* __restrict__ A, int lda, int K,
    const float* __restrict__ W, int ldw,
    const float* __restrict__ bias, const float* __restrict__ rowext,
    float* __restrict__ C, int ldc, int N, int mode,
    int n0, int m0,
    const int* __restrict__ gtok, const float* __restrict__ embW,
    SmemGemm& s)
{
    const int tid  = threadIdx.x;
    const int lane = tid & 31, warp = tid >> 5;
    const int wm = warp & 3, wn = warp >> 2;      // warp tile 32x64
    const int g  = lane >> 2, tg = lane & 3;

    const int ar = tid >> 1,  ac = (tid & 1) * 8;
    const int wr = tid >> 4,  wc = (tid & 15) * 8;
    const bool wp0 = (n0 + wc)     < N;
    const bool wp1 = (n0 + wc + 4) < N;
    const float* asrc;
    if (gtok){
        int t = m0 >> 7;
        int tok = gtok[ar*Tt + t];
        asrc = embW + (size_t)tok*Ee + ac;
    } else {
        asrc = A + (size_t)(m0+ar)*lda + ac;
    }
    const float* wsrc = W + (size_t)wr*ldw + n0 + wc;

    float acc[2][8][4];
    #pragma unroll
    for (int mi=0;mi<2;mi++)
        #pragma unroll
        for (int ni=0;ni<8;ni++)
            #pragma unroll
            for (int j=0;j<4;j++) acc[mi][ni][j]=0.f;

    const int nk = K >> 4;
    #pragma unroll
    for (int st2=0; st2<3; ++st2){
        cp16 (&s.As[st2][ar][ac],   asrc + st2*16);
        cp16 (&s.As[st2][ar][ac+4], asrc + st2*16 + 4);
        cp16p(&s.Ws[st2][wr][wc],   wp0 ? (wsrc + (size_t)(st2*16)*ldw)     : W, wp0);
        cp16p(&s.Ws[st2][wr][wc+4], wp1 ? (wsrc + (size_t)(st2*16)*ldw + 4) : W, wp1);
        cp_commit();
    }

    for (int kt=0; kt<nk; ++kt){
        cp_wait2();
        __syncthreads();
        int kn = kt + 3;
        if (kn < nk){
            int sn = kn & 3;
            cp16 (&s.As[sn][ar][ac],   asrc + kn*16);
            cp16 (&s.As[sn][ar][ac+4], asrc + kn*16 + 4);
            cp16p(&s.Ws[sn][wr][wc],   wp0 ? (wsrc + (size_t)(kn*16)*ldw)     : W, wp0);
            cp16p(&s.Ws[sn][wr][wc+4], wp1 ? (wsrc + (size_t)(kn*16)*ldw + 4) : W, wp1);
        }
        cp_commit();
        const int st = kt & 3;
        #pragma unroll
        for (int kk=0; kk<2; ++kk){
            const int kc = kk*8 + tg;
            uint32_t afr[2][4];
            #pragma unroll
            for (int mi=0; mi<2; ++mi){
                const int rr = wm*32 + mi*16 + g;
                afr[mi][0] = __float_as_uint(s.As[st][rr  ][kc  ]);
                afr[mi][1] = __float_as_uint(s.As[st][rr+8][kc  ]);
                afr[mi][2] = __float_as_uint(s.As[st][rr  ][kc+4]);
                afr[mi][3] = __float_as_uint(s.As[st][rr+8][kc+4]);
            }
            #pragma unroll
            for (int ni=0; ni<8; ++ni){
                const int nc = wn*64 + ni*8 + g;
                uint32_t b0 = __float_as_uint(s.Ws[st][kc  ][nc]);
                uint32_t b1 = __float_as_uint(s.Ws[st][kc+4][nc]);
                #pragma unroll
                for (int mi=0; mi<2; ++mi){
                    asm volatile(
                        "mma.sync.aligned.m16n8k8.row.col.f32.tf32.tf32.f32 "
                        "{%0,%1,%2,%3}, {%4,%5,%6,%7}, {%8,%9}, {%0,%1,%2,%3};\n"
                        : "+f"(acc[mi][ni][0]), "+f"(acc[mi][ni][1]),
                          "+f"(acc[mi][ni][2]), "+f"(acc[mi][ni][3])
                        : "r"(afr[mi][0]), "r"(afr[mi][1]),
                          "r"(afr[mi][2]), "r"(afr[mi][3]), "r"(b0), "r"(b1));
                }
            }
        }
    }
    cp_wait0();
    __syncthreads();

    #pragma unroll
    for (int mi=0; mi<2; ++mi){
        const int grow0 = m0 + wm*32 + mi*16 + g;
        const int grow1 = grow0 + 8;
        size_t drow0, drow1;
        if (mode & MODE_REMAP){
            drow0 = (size_t)((grow0 & 127)*Tt + (grow0 >> 7));
            drow1 = (size_t)((grow1 & 127)*Tt + (grow1 >> 7));
        } else { drow0 = (size_t)grow0; drow1 = (size_t)grow1; }
        float* C0 = C + drow0*ldc;
        float* C1 = C + drow1*ldc;
        #pragma unroll
        for (int ni=0; ni<8; ++ni){
            const int gcol = n0 + wn*64 + ni*8 + 2*tg;
            if (gcol >= N) continue;
            float v00=acc[mi][ni][0], v01=acc[mi][ni][1];
            float v10=acc[mi][ni][2], v11=acc[mi][ni][3];
            if (bias){
                float b0v = bias[gcol], b1v = bias[gcol+1];
                v00+=b0v; v01+=b1v; v10+=b0v; v11+=b1v;
            }
            if (rowext){
                const float* r0 = rowext + (size_t)(grow0 & 127)*4096;
                const float* r1 = rowext + (size_t)(grow1 & 127)*4096;
                v00 += r0[gcol]; v01 += r0[gcol+1];
                v10 += r1[gcol]; v11 += r1[gcol+1];
            }
            if (mode & MODE_LEAKY){
                v00 = roundtf(v00 > 0.f ? v00 : 0.01f*v00);
                v01 = roundtf(v01 > 0.f ? v01 : 0.01f*v01);
                v10 = roundtf(v10 > 0.f ? v10 : 0.01f*v10);
                v11 = roundtf(v11 > 0.f ? v11 : 0.01f*v11);
            }
            C0[gcol] = v00; C0[gcol+1] = v01;
            C1[gcol] = v10; C1[gcol+1] = v11;
        }
    }
}

__global__ __launch_bounds__(256) void gemm128k(
    const float* __restrict__ A, int lda, int K,
    const float* __restrict__ W, int ldw,
    const float* __restrict__ bias, const float* __restrict__ rowext,
    float* __restrict__ C, int ldc, int N, int mode,
    const int* __restrict__ gtok, const float* __restrict__ embW)
{
    __shared__ SmemGemm s;
    gemm128_body(A, lda, K, W, ldw, bias, rowext, C, ldc, N, mode,
                 blockIdx.x*128, blockIdx.y*128, gtok, embW, s);
}

__global__ __launch_bounds__(256) void head_kernel(const float* __restrict__ bp)
{
    __shared__ SmemGemm s;
    const int cta = blockIdx.x;
    if (cta < 8){
        gemm128_body(g_featin, Ff, Ff, g_wbuf + OF_WP, Hh, bp, nullptr,
                     g_feat, Hh, Hh, MODE_LEAKY, cta*128, 0, nullptr, nullptr, s);
    }
    __syncthreads();
    if (threadIdx.x == 0){
        __threadfence();
        atomicAdd(&g_hbar, 1u);
        unsigned v;
        do {
            asm volatile("ld.acquire.gpu.u32 %0, [%1];" : "=r"(v) : "l"(&g_hbar) : "memory");
            if (v < 40u) __nanosleep(200);
        } while (v < 40u);
    }
    __syncthreads();
    if (cta >= 8){
        gemm128_body(g_feat, Hh, Hh, g_wbuf + OF_W0I + (size_t)512*4096, 4096,
                     g_bias0i, nullptr, g_prefeat, 4096, 4096, 0,
                     (cta-8)*128, 0, nullptr, nullptr, s);
    }
}

// ---------------- persistent recurrence ----------------
#define NCTA 256u

__device__ __forceinline__ void gridbar(unsigned &ep, int cta){
    __syncthreads();
    ep += 1;
    if (threadIdx.x == 0){
        __threadfence();
        const int grp = cta >> 5;                 // 8 groups of 32
        unsigned* gc = &g_bgrp[grp*64];
        atomicAdd(gc, 1u);
        unsigned v;
        if ((cta & 31) == 0){
            do {
                asm volatile("ld.acquire.gpu.u32 %0, [%1];" : "=r"(v) : "l"(gc) : "memory");
                if (v < ep*32u) __nanosleep(128);
            } while (v < ep*32u);
            __threadfence();   // release: carry group's writes into the root add
            atomicAdd(&g_barc, 1u);
        }
        do {
            asm volatile("ld.acquire.gpu.u32 %0, [%1];" : "=r"(v) : "l"(&g_barc) : "memory");
            if (v < ep*8u) __nanosleep(128);
        } while (v < ep*8u);
    }
    __syncthreads();
}

__device__ __forceinline__ void gemm_tile_dev(
    const float* __restrict__ A, int lda,
    const float* __restrict__ W, int ldw,
    int m0, int n0, int kbase, int nk,
    float (&As)[4][64][20], float (&Ws)[4][16][72],
    float acc[4][4])
{
    const int tid  = threadIdx.x;
    const int lane = tid & 31, warp = tid >> 5;
    const int wm = warp & 3, wn = warp >> 2;
    const int g  = lane >> 2, tg = lane & 3;
    const int ar = tid >> 2,  ac = (tid & 3)  * 4;
    const int wr = tid >> 4,  wc = (tid & 15) * 4;
    const float* asrc = A + (size_t)(m0+ar)*lda + kbase + ac;
    const float* wsrc = W + (size_t)(kbase+wr)*ldw + n0 + wc;

    #pragma unroll
    for (int i=0;i<4;i++){
        #pragma unroll
        for (int j=0;j<4;j++) acc[i][j]=0.f;
    }

    #pragma unroll
    for (int st2=0; st2<3; ++st2){
        cp16(&As[st2][ar][ac], asrc + st2*16);
        cp16(&Ws[st2][wr][wc], wsrc + (size_t)(st2*16)*ldw);
        cp_commit();
    }
    for (int kt=0; kt<nk; ++kt){
        cp_wait2();
        __syncthreads();
        int kn = kt + 3;
        if (kn < nk){
            int sn = kn & 3;
            cp16(&As[sn][ar][ac], asrc + kn*16);
            cp16(&Ws[sn][wr][wc], wsrc + (size_t)(kn*16)*ldw);
        }
        cp_commit();
        const int st = kt & 3;
        const int rr = wm*16 + g;
        #pragma unroll
        for (int kk=0; kk<2; ++kk){
            const int kc = kk*8 + tg;
            uint32_t a0 = __float_as_uint(As[st][rr  ][kc  ]);
            uint32_t a1 = __float_as_uint(As[st][rr+8][kc  ]);
            uint32_t a2 = __float_as_uint(As[st][rr  ][kc+4]);
            uint32_t a3 = __float_as_uint(As[st][rr+8][kc+4]);
            #pragma unroll
            for (int ni=0; ni<4; ++ni){
                const int nc = wn*32 + ni*8 + g;
                uint32_t b0 = __float_as_uint(Ws[st][kc  ][nc]);
                uint32_t b1 = __float_as_uint(Ws[st][kc+4][nc]);
                asm volatile(
                    "mma.sync.aligned.m16n8k8.row.col.f32.tf32.tf32.f32 "
                    "{%0,%1,%2,%3}, {%4,%5,%6,%7}, {%8,%9}, {%0,%1,%2,%3};\n"
                    : "+f"(acc[ni][0]), "+f"(acc[ni][1]),
                      "+f"(acc[ni][2]), "+f"(acc[ni][3])
                    : "r"(a0), "r"(a1), "r"(a2), "r"(a3), "r"(b0), "r"(b1));
            }
        }
    }
    cp_wait0();
    __syncthreads();
}

__device__ __forceinline__ void store_partial(float acc[4][4], int tile,
                                              int wm, int wn, int g, int tg)
{
    float* gp = g_part + (size_t)tile*4096;
    const int lr0 = wm*16 + g, lr1 = lr0 + 8;
    #pragma unroll
    for (int ni=0; ni<4; ++ni){
        const int lc = wn*32 + ni*8 + 2*tg;
        gp[lr0*64 + lc]   = acc[ni][0];
        gp[lr0*64 + lc+1] = acc[ni][1];
        gp[lr1*64 + lc]   = acc[ni][2];
        gp[lr1*64 + lc+1] = acc[ni][3];
    }
}

__device__ __forceinline__ void lstm_epi(float acc[4][4], int tile, int t,
    const float* rowext, const float* colext,
    float* cbuf, int hoff, bool write_hs,
    int m0, int n0, int nb, int wm, int wn, int g, int tg)
{
    const float* gp = g_part + (size_t)tile*4096;
    const int lr0 = wm*16 + g, lr1 = lr0 + 8;
    const int grow0 = m0 + lr0, grow1 = m0 + lr1;
    #pragma unroll
    for (int ni=0; ni<4; ++ni){
        const int lc = wn*32 + ni*8 + 2*tg;
        const int gcol = n0 + lc;
        float v00 = acc[ni][0] + gp[lr0*64 + lc];
        float v01 = acc[ni][1] + gp[lr0*64 + lc+1];
        float v10 = acc[ni][2] + gp[lr1*64 + lc];
        float v11 = acc[ni][3] + gp[lr1*64 + lc+1];
        if (rowext){
            v00 += rowext[(size_t)grow0*4096 + gcol];
            v01 += rowext[(size_t)grow0*4096 + gcol+1];
            v10 += rowext[(size_t)grow1*4096 + gcol];
            v11 += rowext[(size_t)grow1*4096 + gcol+1];
        } else {
            float b0 = colext[gcol], b1 = colext[gcol+1];
            v00+=b0; v01+=b1; v10+=b0; v11+=b1;
        }
        float p00 = __shfl_xor_sync(0xffffffffu, v00, 1);
        float p01 = __shfl_xor_sync(0xffffffffu, v01, 1);
        float p10 = __shfl_xor_sync(0xffffffffu, v10, 1);
        float p11 = __shfl_xor_sync(0xffffffffu, v11, 1);
        if ((tg & 1) == 0){
            const int h = nb*16 + wn*8 + ni*2 + (tg >> 1);
            {
                float f = sigf(v00), ii = sigf(v01);
                float o = sigf(p00), gg = tanhf(p01);
                float c = f*cbuf[grow0*1024 + h] + ii*gg;
                cbuf[grow0*1024 + h] = c;
                float hn = roundtf(o * tanhf(c));
                g_comb1[grow0*2048 + hoff + h] = hn;
                if (write_hs) g_hs[(size_t)t*(Bb*Hh) + grow0*1024 + h] = hn;
            }
            {
                float f = sigf(v10), ii = sigf(v11);
                float o = sigf(p10), gg = tanhf(p11);
                float c = f*cbuf[grow1*1024 + h] + ii*gg;
                cbuf[grow1*1024 + h] = c;
                float hn = roundtf(o * tanhf(c));
                g_comb1[grow1*2048 + hoff + h] = hn;
                if (write_hs) g_hs[(size_t)t*(Bb*Hh) + grow1*1024 + h] = hn;
            }
        }
    }
}

__global__ __launch_bounds__(256, 2) void lstm_persistent()
{
    __shared__ __align__(16) float As[4][64][20];
    __shared__ __align__(16) float Ws[4][16][72];

    const int cta  = blockIdx.x;
    const int ks   = cta & 1;
    const int tile = cta >> 1;
    const int mb   = tile & 1, nb = tile >> 1;
    const int m0   = mb*64,   n0 = nb*64;
    const int tid  = threadIdx.x;
    const int lane = tid & 31, warp = tid >> 5;
    const int wm = warp & 3, wn = warp >> 2;
    const int g  = lane >> 2, tg = lane & 3;

    const float* Wrec0 = g_wbuf + OF_W0I + (size_t)1536*4096;
    const float* W1    = g_wbuf + OF_W1I;

    unsigned ep = 0;
    float acc[4][4];

    for (int t = 0; t < Tt; ++t){
        gemm_tile_dev(g_comb1, 2048, Wrec0, 4096, m0, n0, ks*512, 32, As, Ws, acc);
        if (ks == 1) store_partial(acc, tile, wm, wn, g, tg);
        gridbar(ep, cta);
        if (ks == 0)
            lstm_epi(acc, tile, t, g_pre0 + (size_t)t*(Bb*4096), nullptr,
                     g_c0, 0, false, m0, n0, nb, wm, wn, g, tg);
        gridbar(ep, cta);
        gemm_tile_dev(g_comb1, 2048, W1, 4096, m0, n0, ks*1024, 64, As, Ws, acc);
        if (ks == 1) store_partial(acc, tile, wm, wn, g, tg);
        gridbar(ep, cta);
        if (ks == 0)
            lstm_epi(acc, tile, t, nullptr, g_bias1i,
                     g_c1, 1024, true, m0, n0, nb, wm, wn, g, tg);
        gridbar(ep, cta);
    }
}

// ---------------- host orchestration ----------------
extern "C" void kernel_launch(void* const* d_in, const int* in_sizes, int n_in,
                              void* d_out, int out_size)
{
    const int*   tokens    = (const int*)  d_in[0];
    const float* features  = (const float*)d_in[1];
    const float* embedding = (const float*)d_in[2];
    const float* Wp  = (const float*)d_in[3];
    const float* bp  = (const float*)d_in[4];
    const float* Wf0 = (const float*)d_in[5];  const float* bf0 = (const float*)d_in[6];
    const float* Wi0 = (const float*)d_in[7];  const float* bi0 = (const float*)d_in[8];
    const float* Wo0 = (const float*)d_in[9];  const float* bo0 = (const float*)d_in[10];
    const float* Wg0 = (const float*)d_in[11]; const float* bg0 = (const float*)d_in[12];
    const float* Wf1 = (const float*)d_in[13]; const float* bf1 = (const float*)d_in[14];
    const float* Wi1 = (const float*)d_in[15]; const float* bi1 = (const float*)d_in[16];
    const float* Wo1 = (const float*)d_in[17]; const float* bo1 = (const float*)d_in[18];
    const float* Wg1 = (const float*)d_in[19]; const float* bg1 = (const float*)d_in[20];
    const float* Wout = (const float*)d_in[21];
    const float* bout = (const float*)d_in[22];
    float* out = (float*)d_out;

    float *wb, *pre0, *prefeat, *hs;
    cudaGetSymbolAddress((void**)&wb,      g_wbuf);
    cudaGetSymbolAddress((void**)&pre0,    g_pre0);
    cudaGetSymbolAddress((void**)&prefeat, g_prefeat);
    cudaGetSymbolAddress((void**)&hs,      g_hs);

    // 1) convert + pack + zero (single launch)
    cvt_all<<<(CVT_TOTAL + 255)/256, 256>>>(features, Wp, Wout, embedding,
        Wf0, Wi0, Wo0, Wg0, Wf1, Wi1, Wo1, Wg1,
        bf0, bi0, bo0, bg0, bf1, bi1, bo1, bg1);

    // 2) head: feat projection + prefeat (fused, internal barrier)
    head_kernel<<<40, 256>>>(bp);

    // 3) pre0 = gather(emb) @ W0i[0:512,:] + prefeat[b]   (K=512)
    gemm128k<<<dim3(32,25), 256>>>(nullptr, 0, 512,
        wb + OF_W0I, 4096, nullptr, prefeat,
        pre0, 4096, 4096, 0, tokens, wb + OF_EMB);

    // 4) persistent 25-step recurrence   <-- profiled slot
    lstm_persistent<<<NCTA, 256>>>();

    // 5) logits = hs @ Wout + bout, remap to [B,T,V]
    gemm128k<<<dim3(79,25), 256>>>(hs, Hh, Hh,
        wb + OF_WOUT, Vv, bout, nullptr, out, Vv, Vv, MODE_REMAP,
        nullptr, nullptr);
}